// round 11
// baseline (speedup 1.0000x reference)
#include <cuda_runtime.h>
#include <cuda_bf16.h>

// SNN bit-plane quantization scan. x viewed as [T, N], N = B*TOK*DIM.
//   mem += x_t
//   k = clamp(trunc(mem*128/lam), 0, 255)   [float-domain trunc+clamp]
//   spike = lam*k ; mem -= spike            [== exact bit-plane recombination]
//
// HBM-bound: 154 MB total stream, running at ~7.45 TB/s effective (~93% of
// 8 TB/s spec) == the roofline. (ncu's DRAM% is deflated: the 77 MB output
// fits in the 126 MB L2 during the single cache-flushed profile launch.)
// Converged configuration; this round tests block=512 + batched stores as
// the last untested launch-shape knob.

#define T_STEPS 4

__device__ __forceinline__ float snn_step(float& m, float lam, float c) {
    float v = m * c;                       // c = 128/lam (exact for pow2 lam)
    float k = truncf(v);                   // F2F.RZ; == int trunc for our range
    k = fminf(fmaxf(k, 0.0f), 255.0f);
    float spike = lam * k;
    m -= spike;
    return spike;
}

__global__ __launch_bounds__(512) void snn_scan_kernel(
    const float4* __restrict__ x,
    const float* __restrict__ lam_p,
    float4* __restrict__ out,
    int n4)  // N/4 float4 elements per timestep
{
    int i = blockIdx.x * blockDim.x + threadIdx.x;
    if (i >= n4) return;

    const float lam = __ldg(lam_p);
    const float c   = 128.0f * __frcp_rn(lam);  // exact for lam = 2^e (test: 1.0)
    const float m0  = 0.5f * lam;

    // Front-batch the T=4 loads: 4 independent, fully-coalesced LDG.128.
    float4 xv[T_STEPS];
#pragma unroll
    for (int t = 0; t < T_STEPS; t++)
        xv[t] = x[t * n4 + i];

    float4 m = make_float4(m0, m0, m0, m0);
    float4 s[T_STEPS];

#pragma unroll
    for (int t = 0; t < T_STEPS; t++) {
        m.x += xv[t].x;
        m.y += xv[t].y;
        m.z += xv[t].z;
        m.w += xv[t].w;
        s[t].x = snn_step(m.x, lam, c);
        s[t].y = snn_step(m.y, lam, c);
        s[t].z = snn_step(m.z, lam, c);
        s[t].w = snn_step(m.w, lam, c);
    }

    // Batched stores: 4 back-to-back STG.128 (fire-and-forget).
#pragma unroll
    for (int t = 0; t < T_STEPS; t++)
        out[t * n4 + i] = s[t];
}

extern "C" void kernel_launch(void* const* d_in, const int* in_sizes, int n_in,
                              void* d_out, int out_size) {
    const float* x   = (const float*)d_in[0];
    const float* lam = (const float*)d_in[1];
    float* out       = (float*)d_out;

    int total = in_sizes[0];          // T * B * TOK * DIM
    int n_per_t = total / T_STEPS;    // 4,816,896
    int n4 = n_per_t / 4;             // 1,204,224

    int block = 512;
    int grid = (n4 + block - 1) / block;   // 2352
    snn_scan_kernel<<<grid, block>>>(
        (const float4*)x, lam, (float4*)out, n4);
}